// round 2
// baseline (speedup 1.0000x reference)
#include <cuda_runtime.h>

// ---------------------------------------------------------------------------
// AtomUpdateBlock:
//   x2[a,:]  = sum_{e: id_j[e]=a} m[e,:] * (rbf[e,:] @ W_rbf.T)
//   y0 = ssilu(scale * x2 @ W1.T)
//   for i in 0..1:  h = ssilu(ssilu(y @ Wres[i,0].T) @ Wres[i,1].T)
//                   y = (y + h) * 2^-0.5
//
// Edge stage: CSR build (int atomics only) + atom-major gather (no f32 atomics).
// MLP stage: FFMA2 SIMT GEMM, row-paired accumulators (no per-FMA packing movs).
// ---------------------------------------------------------------------------

#define CAP_ATOMS 131072
#define CAP_EDGES (1 << 21)

__device__ float g_x2[CAP_ATOMS * 128];
__device__ float g_a [CAP_ATOMS * 128];
__device__ float g_b [CAP_ATOMS * 128];
__device__ int   g_counts[CAP_ATOMS];
__device__ int   g_offs  [CAP_ATOMS + 1];
__device__ int   g_cursor[CAP_ATOMS];
__device__ int   g_bsums [256];
__device__ int   g_eids  [CAP_EDGES];

__device__ __forceinline__ float ssilu(float x) {
    return x * (1.0f / (1.0f + __expf(-x))) * 1.6666666666666667f;
}

// ---------------------------------------------------------------------------
// CSR build
// ---------------------------------------------------------------------------
__global__ void __launch_bounds__(256) zero_int_kernel(int* __restrict__ p, int n4) {
    int i = blockIdx.x * blockDim.x + threadIdx.x;
    int stride = gridDim.x * blockDim.x;
    int4 z = make_int4(0, 0, 0, 0);
    for (; i < n4; i += stride) ((int4*)p)[i] = z;
}

__global__ void __launch_bounds__(256) hist_kernel(const int* __restrict__ idj,
                                                   int* __restrict__ counts, int E) {
    int i = blockIdx.x * blockDim.x + threadIdx.x;
    int stride = gridDim.x * blockDim.x;
    for (; i < E; i += stride) atomicAdd(&counts[__ldg(idj + i)], 1);
}

// block scans 1024 atoms (256 threads x 4); writes block-local exclusive offsets
__global__ void __launch_bounds__(256) scan1_kernel(const int* __restrict__ counts,
                                                    int* __restrict__ offs,
                                                    int* __restrict__ bsums, int nAtoms) {
    __shared__ int sm[256];
    int t = threadIdx.x;
    int base = blockIdx.x * 1024 + t * 4;
    int c0 = 0, c1 = 0, c2 = 0, c3 = 0;
    if (base + 3 < nAtoms) {
        int4 c = *(const int4*)(counts + base);
        c0 = c.x; c1 = c.y; c2 = c.z; c3 = c.w;
    } else {
        if (base + 0 < nAtoms) c0 = counts[base + 0];
        if (base + 1 < nAtoms) c1 = counts[base + 1];
        if (base + 2 < nAtoms) c2 = counts[base + 2];
        if (base + 3 < nAtoms) c3 = counts[base + 3];
    }
    int T = c0 + c1 + c2 + c3;
    sm[t] = T;
    __syncthreads();
    for (int d = 1; d < 256; d <<= 1) {
        int v = (t >= d) ? sm[t - d] : 0;
        __syncthreads();
        sm[t] += v;
        __syncthreads();
    }
    int o = sm[t] - T;   // block-local exclusive
    if (t == 255) bsums[blockIdx.x] = sm[255];
    if (base + 0 < nAtoms) offs[base + 0] = o; o += c0;
    if (base + 1 < nAtoms) offs[base + 1] = o; o += c1;
    if (base + 2 < nAtoms) offs[base + 2] = o; o += c2;
    if (base + 3 < nAtoms) offs[base + 3] = o;
}

// exclusive scan of <=128 block sums, single block of 128 threads
__global__ void __launch_bounds__(128) scan2_kernel(int* __restrict__ bsums, int nb) {
    __shared__ int sm[128];
    int t = threadIdx.x;
    int v = (t < nb) ? bsums[t] : 0;
    sm[t] = v;
    __syncthreads();
    for (int d = 1; d < 128; d <<= 1) {
        int x = (t >= d) ? sm[t - d] : 0;
        __syncthreads();
        sm[t] += x;
        __syncthreads();
    }
    bsums[t] = sm[t] - v;   // exclusive
}

__global__ void __launch_bounds__(256) scan3_kernel(const int* __restrict__ bsums,
                                                    int* __restrict__ offs,
                                                    int* __restrict__ cursor,
                                                    int nAtoms, int E) {
    int i = blockIdx.x * blockDim.x + threadIdx.x;
    if (i < nAtoms) {
        int v = offs[i] + __ldg(bsums + (i >> 10));
        offs[i] = v;
        cursor[i] = v;
    }
    if (i == 0) offs[nAtoms] = E;
}

__global__ void __launch_bounds__(256) fill_kernel(const int* __restrict__ idj,
                                                   int* __restrict__ cursor,
                                                   int* __restrict__ eids, int E) {
    int i = blockIdx.x * blockDim.x + threadIdx.x;
    int stride = gridDim.x * blockDim.x;
    for (; i < E; i += stride) {
        int a = __ldg(idj + i);
        int p = atomicAdd(&cursor[a], 1);
        eids[p] = i;
    }
}

// ---------------------------------------------------------------------------
// Gather kernel: warp per atom. Lane L owns channels 4L..4L+3.
// W_rbf rows packed (f32x2) in registers; per edge: 32 FFMA2 dot + m-load +
// 4 scalar FFMA accumulate. One STG.128 per lane per atom. No f32 atomics.
// ---------------------------------------------------------------------------
__global__ void __launch_bounds__(256) gather_kernel(
    const float* __restrict__ m,      // [E,128]
    const float* __restrict__ rbf,    // [E,16]
    const int*   __restrict__ eids,   // [E] grouped by atom
    const int*   __restrict__ offs,   // [nAtoms+1]
    const float* __restrict__ Wr,     // [128,16]
    float*       __restrict__ out,    // [nAtoms,128]
    int nAtoms)
{
    const int lane   = threadIdx.x & 31;
    const int gwarp  = (blockIdx.x * blockDim.x + threadIdx.x) >> 5;
    const int nwarps = (gridDim.x * blockDim.x) >> 5;
    const int c0 = lane * 4;

    unsigned long long wp0[16], wp1[16];
#pragma unroll
    for (int k = 0; k < 16; ++k) {
        float a = __ldg(&Wr[(c0 + 0) * 16 + k]);
        float b = __ldg(&Wr[(c0 + 1) * 16 + k]);
        float c = __ldg(&Wr[(c0 + 2) * 16 + k]);
        float d = __ldg(&Wr[(c0 + 3) * 16 + k]);
        asm("mov.b64 %0, {%1, %2};" : "=l"(wp0[k]) : "f"(a), "f"(b));
        asm("mov.b64 %0, {%1, %2};" : "=l"(wp1[k]) : "f"(c), "f"(d));
    }

    for (int atom = gwarp; atom < nAtoms; atom += nwarps) {
        const int s   = __ldg(offs + atom);
        const int end = __ldg(offs + atom + 1);
        float ax = 0.f, ay = 0.f, az = 0.f, aw = 0.f;

        for (int i = s; i < end; ++i) {
            const int e = __ldg(eids + i);
            const float4* rb4 = (const float4*)(rbf + (size_t)e * 16);
            float4 r0 = __ldg(rb4 + 0);
            float4 r1 = __ldg(rb4 + 1);
            float4 r2 = __ldg(rb4 + 2);
            float4 r3 = __ldg(rb4 + 3);
            float4 mv = __ldg((const float4*)(m + (size_t)e * 128) + lane);

            float rk[16];
            rk[0]=r0.x; rk[1]=r0.y; rk[2]=r0.z; rk[3]=r0.w;
            rk[4]=r1.x; rk[5]=r1.y; rk[6]=r1.z; rk[7]=r1.w;
            rk[8]=r2.x; rk[9]=r2.y; rk[10]=r2.z; rk[11]=r2.w;
            rk[12]=r3.x; rk[13]=r3.y; rk[14]=r3.z; rk[15]=r3.w;

            unsigned long long d01 = 0ull, d23 = 0ull;
#pragma unroll
            for (int k = 0; k < 16; ++k) {
                unsigned long long rp;
                asm("mov.b64 %0, {%1, %1};" : "=l"(rp) : "f"(rk[k]));
                asm("fma.rn.f32x2 %0, %1, %2, %0;" : "+l"(d01) : "l"(rp), "l"(wp0[k]));
                asm("fma.rn.f32x2 %0, %1, %2, %0;" : "+l"(d23) : "l"(rp), "l"(wp1[k]));
            }
            float v0, v1, v2, v3;
            asm("mov.b64 {%0, %1}, %2;" : "=f"(v0), "=f"(v1) : "l"(d01));
            asm("mov.b64 {%0, %1}, %2;" : "=f"(v2), "=f"(v3) : "l"(d23));
            ax = fmaf(v0, mv.x, ax);
            ay = fmaf(v1, mv.y, ay);
            az = fmaf(v2, mv.z, az);
            aw = fmaf(v3, mv.w, aw);
        }
        *(float4*)(out + (size_t)atom * 128 + c0) = make_float4(ax, ay, az, aw);
    }
}

// ---------------------------------------------------------------------------
// MLP GEMM: out[r,c] = post( sum_k X[r,k] * W[c,k] )
// BM=64 rows, BN=128. 256 threads, thread tile 8 rows x 4 cols.
// Row-paired f32x2 accumulators: A pairs come straight out of smem as 64-bit
// words (no packing movs); only 4 W-dup movs per k per thread.
// ---------------------------------------------------------------------------
#define MLP_SMEM_BYTES ((128 * 68 + 128 * 132) * 4)

__global__ void __launch_bounds__(256, 2) mlp_kernel(
    const float* __restrict__ X,          // [nRows,128]
    const float* __restrict__ W,          // [128,128] row-major [out,in]
    const float* __restrict__ res,        // [nRows,128] or null
    const float* __restrict__ scale_ptr,  // scalar or null
    float*       __restrict__ out,        // [nRows,128]
    int nRows)
{
    extern __shared__ float smem[];
    float* As = smem;                 // [128][68]  As[k][r]
    float* Ws = smem + 128 * 68;      // [128][132] Ws[k][c]

    const int tid  = threadIdx.x;
    const int row0 = blockIdx.x * 64;
    const float pre = scale_ptr ? __ldg(scale_ptr) : 1.0f;

    // load W transposed (coalesced over k; STS.128 conflict-free)
    for (int i = tid; i < 32 * 128; i += 256) {
        int c4 = i >> 7, k = i & 127;
        float w0 = __ldg(&W[(4 * c4 + 0) * 128 + k]);
        float w1 = __ldg(&W[(4 * c4 + 1) * 128 + k]);
        float w2 = __ldg(&W[(4 * c4 + 2) * 128 + k]);
        float w3 = __ldg(&W[(4 * c4 + 3) * 128 + k]);
        *(float4*)&Ws[k * 132 + 4 * c4] = make_float4(w0, w1, w2, w3);
    }
    // load A transposed
    for (int i = tid; i < 16 * 128; i += 256) {
        int r4 = i >> 7, k = i & 127;
        int r = 4 * r4;
        float a0 = (row0 + r + 0 < nRows) ? X[(size_t)(row0 + r + 0) * 128 + k] : 0.f;
        float a1 = (row0 + r + 1 < nRows) ? X[(size_t)(row0 + r + 1) * 128 + k] : 0.f;
        float a2 = (row0 + r + 2 < nRows) ? X[(size_t)(row0 + r + 2) * 128 + k] : 0.f;
        float a3 = (row0 + r + 3 < nRows) ? X[(size_t)(row0 + r + 3) * 128 + k] : 0.f;
        *(float4*)&As[k * 68 + r] = make_float4(a0, a1, a2, a3);
    }
    __syncthreads();

    const int c0 = (tid & 31) * 4;        // 4 consecutive cols
    const int r0 = (tid >> 5) * 8;        // 8 consecutive rows (warp-uniform)

    // acc[rp][c] = f32x2 over rows {r0+2rp, r0+2rp+1}, column c0+c
    unsigned long long acc[4][4];
#pragma unroll
    for (int rp = 0; rp < 4; ++rp)
#pragma unroll
        for (int c = 0; c < 4; ++c) acc[rp][c] = 0ull;

#pragma unroll 4
    for (int k = 0; k < 128; ++k) {
        float4 wv = *(const float4*)&Ws[k * 132 + c0];         // 4 cols
        ulonglong2 a01 = *(const ulonglong2*)&As[k * 68 + r0];     // rows 0..3
        ulonglong2 a23 = *(const ulonglong2*)&As[k * 68 + r0 + 4]; // rows 4..7
        unsigned long long ap[4] = {a01.x, a01.y, a23.x, a23.y};
        unsigned long long wd[4];
        asm("mov.b64 %0, {%1, %1};" : "=l"(wd[0]) : "f"(wv.x));
        asm("mov.b64 %0, {%1, %1};" : "=l"(wd[1]) : "f"(wv.y));
        asm("mov.b64 %0, {%1, %1};" : "=l"(wd[2]) : "f"(wv.z));
        asm("mov.b64 %0, {%1, %1};" : "=l"(wd[3]) : "f"(wv.w));
#pragma unroll
        for (int rp = 0; rp < 4; ++rp)
#pragma unroll
            for (int c = 0; c < 4; ++c)
                asm("fma.rn.f32x2 %0, %1, %2, %0;"
                    : "+l"(acc[rp][c]) : "l"(ap[rp]), "l"(wd[c]));
    }

    const float inv_sqrt2 = 0.70710678118654752440f;
#pragma unroll
    for (int rp = 0; rp < 4; ++rp) {
        int ra = row0 + r0 + 2 * rp;
        int rb = ra + 1;
        float la[4], lb[4];
#pragma unroll
        for (int c = 0; c < 4; ++c)
            asm("mov.b64 {%0, %1}, %2;" : "=f"(la[c]), "=f"(lb[c]) : "l"(acc[rp][c]));

        if (ra < nRows) {
            float4 y;
            y.x = ssilu(pre * la[0]);
            y.y = ssilu(pre * la[1]);
            y.z = ssilu(pre * la[2]);
            y.w = ssilu(pre * la[3]);
            if (res) {
                float4 rv = *(const float4*)&res[(size_t)ra * 128 + c0];
                y.x = (rv.x + y.x) * inv_sqrt2;
                y.y = (rv.y + y.y) * inv_sqrt2;
                y.z = (rv.z + y.z) * inv_sqrt2;
                y.w = (rv.w + y.w) * inv_sqrt2;
            }
            *(float4*)&out[(size_t)ra * 128 + c0] = y;
        }
        if (rb < nRows) {
            float4 y;
            y.x = ssilu(pre * lb[0]);
            y.y = ssilu(pre * lb[1]);
            y.z = ssilu(pre * lb[2]);
            y.w = ssilu(pre * lb[3]);
            if (res) {
                float4 rv = *(const float4*)&res[(size_t)rb * 128 + c0];
                y.x = (rv.x + y.x) * inv_sqrt2;
                y.y = (rv.y + y.y) * inv_sqrt2;
                y.z = (rv.z + y.z) * inv_sqrt2;
                y.w = (rv.w + y.w) * inv_sqrt2;
            }
            *(float4*)&out[(size_t)rb * 128 + c0] = y;
        }
    }
}

// ---------------------------------------------------------------------------
extern "C" void kernel_launch(void* const* d_in, const int* in_sizes, int n_in,
                              void* d_out, int out_size)
{
    // metadata order: nAtoms, m, rbf, id_j, W_rbf, scale, W1, W_res
    const float* m     = (const float*)d_in[1];
    const float* rbf   = (const float*)d_in[2];
    const int*   idj   = (const int*)  d_in[3];
    const float* Wrbf  = (const float*)d_in[4];
    const float* scale = (const float*)d_in[5];
    const float* W1    = (const float*)d_in[6];
    const float* Wres  = (const float*)d_in[7];

    int E      = in_sizes[1] / 128;
    int nAtoms = out_size / 128;
    if (nAtoms > CAP_ATOMS) nAtoms = CAP_ATOMS;
    if (E > CAP_EDGES) E = CAP_EDGES;

    float *px2 = nullptr, *pa = nullptr, *pb = nullptr;
    int *pcounts = nullptr, *poffs = nullptr, *pcursor = nullptr,
        *pbsums = nullptr, *peids = nullptr;
    cudaGetSymbolAddress((void**)&px2, g_x2);
    cudaGetSymbolAddress((void**)&pa,  g_a);
    cudaGetSymbolAddress((void**)&pb,  g_b);
    cudaGetSymbolAddress((void**)&pcounts, g_counts);
    cudaGetSymbolAddress((void**)&poffs,   g_offs);
    cudaGetSymbolAddress((void**)&pcursor, g_cursor);
    cudaGetSymbolAddress((void**)&pbsums,  g_bsums);
    cudaGetSymbolAddress((void**)&peids,   g_eids);

    cudaFuncSetAttribute(mlp_kernel, cudaFuncAttributeMaxDynamicSharedMemorySize,
                         MLP_SMEM_BYTES);

    // ---- CSR build ----
    zero_int_kernel<<<256, 256>>>(pcounts, CAP_ATOMS / 4);
    hist_kernel<<<2048, 256>>>(idj, pcounts, E);
    int nb = (nAtoms + 1023) / 1024;
    scan1_kernel<<<nb, 256>>>(pcounts, poffs, pbsums, nAtoms);
    scan2_kernel<<<1, 128>>>(pbsums, nb);
    scan3_kernel<<<(nAtoms + 255) / 256, 256>>>(pbsums, poffs, pcursor, nAtoms, E);
    fill_kernel<<<2048, 256>>>(idj, pcursor, peids, E);

    // ---- gather (edge stage) ----
    int gblocks = (nAtoms + 7) / 8;   // warp per atom
    gather_kernel<<<gblocks, 256>>>(m, rbf, peids, poffs, Wrbf, px2, nAtoms);

    // ---- MLP chain ----
    int grid = (nAtoms + 63) / 64;
    float* dout = (float*)d_out;
    mlp_kernel<<<grid, 256, MLP_SMEM_BYTES>>>(px2, W1, nullptr, scale, pa, nAtoms);
    mlp_kernel<<<grid, 256, MLP_SMEM_BYTES>>>(pa, Wres + 0 * 16384, nullptr, nullptr, pb, nAtoms);
    mlp_kernel<<<grid, 256, MLP_SMEM_BYTES>>>(pb, Wres + 1 * 16384, pa, nullptr, px2, nAtoms);
    mlp_kernel<<<grid, 256, MLP_SMEM_BYTES>>>(px2, Wres + 2 * 16384, nullptr, nullptr, pb, nAtoms);
    mlp_kernel<<<grid, 256, MLP_SMEM_BYTES>>>(pb, Wres + 3 * 16384, px2, nullptr, dout, nAtoms);
}

// round 4
// speedup vs baseline: 1.2499x; 1.2499x over previous
#include <cuda_runtime.h>
#include <cuda_bf16.h>
#include <cstdint>

// ---------------------------------------------------------------------------
// AtomUpdateBlock on GB300 (plain sm_103 feature set: HMMA via mma.sync).
// Edge stage (R1-proven): zero + warp-per-edge FFMA2 + red.global.add.v4.f32.
// MLP stage: bf16-split GEMM on mma.sync.m16n8k16 (D = AhBh + AlBh + AhBl).
// ---------------------------------------------------------------------------

#define CAP_ATOMS 131072
__device__ float g_x2[CAP_ATOMS * 128];
__device__ float g_a [CAP_ATOMS * 128];
__device__ float g_b [CAP_ATOMS * 128];

__device__ __forceinline__ float ssilu(float x) {
    return x * (1.0f / (1.0f + __expf(-x))) * 1.6666666666666667f;
}

// ============================ edge stage ====================================
__global__ void __launch_bounds__(256) zero_kernel(float* __restrict__ p, int n4) {
    int i = blockIdx.x * blockDim.x + threadIdx.x;
    int stride = gridDim.x * blockDim.x;
    float4 z = make_float4(0.f, 0.f, 0.f, 0.f);
    for (; i < n4; i += stride) ((float4*)p)[i] = z;
}

__global__ void __launch_bounds__(256) edge_kernel(
    const float* __restrict__ m,      // [E,128]
    const float* __restrict__ rbf,    // [E,16]
    const int*   __restrict__ idj,    // [E]
    const float* __restrict__ Wr,     // [128,16]
    float*       __restrict__ out,    // [nAtoms,128]
    int E)
{
    const int lane  = threadIdx.x & 31;
    const int warp  = (blockIdx.x * blockDim.x + threadIdx.x) >> 5;
    const int nwarp = (gridDim.x * blockDim.x) >> 5;
    const int c0 = lane * 4;

    unsigned long long wp0[16], wp1[16];
#pragma unroll
    for (int k = 0; k < 16; ++k) {
        float a = Wr[(c0 + 0) * 16 + k];
        float b = Wr[(c0 + 1) * 16 + k];
        float c = Wr[(c0 + 2) * 16 + k];
        float d = Wr[(c0 + 3) * 16 + k];
        asm("mov.b64 %0, {%1, %2};" : "=l"(wp0[k]) : "f"(a), "f"(b));
        asm("mov.b64 %0, {%1, %2};" : "=l"(wp1[k]) : "f"(c), "f"(d));
    }

    for (int e = warp; e < E; e += nwarp) {
        const int atom = __ldg(idj + e);
        const float4* rb4 = (const float4*)(rbf + (size_t)e * 16);
        float4 r0 = __ldg(rb4 + 0);
        float4 r1 = __ldg(rb4 + 1);
        float4 r2 = __ldg(rb4 + 2);
        float4 r3 = __ldg(rb4 + 3);
        float rk[16];
        rk[0]=r0.x; rk[1]=r0.y; rk[2]=r0.z; rk[3]=r0.w;
        rk[4]=r1.x; rk[5]=r1.y; rk[6]=r1.z; rk[7]=r1.w;
        rk[8]=r2.x; rk[9]=r2.y; rk[10]=r2.z; rk[11]=r2.w;
        rk[12]=r3.x; rk[13]=r3.y; rk[14]=r3.z; rk[15]=r3.w;

        unsigned long long acc0 = 0ull, acc1 = 0ull;
#pragma unroll
        for (int k = 0; k < 16; ++k) {
            unsigned long long rp;
            asm("mov.b64 %0, {%1, %1};" : "=l"(rp) : "f"(rk[k]));
            asm("fma.rn.f32x2 %0, %1, %2, %0;" : "+l"(acc0) : "l"(rp), "l"(wp0[k]));
            asm("fma.rn.f32x2 %0, %1, %2, %0;" : "+l"(acc1) : "l"(rp), "l"(wp1[k]));
        }

        float4 mv = __ldg((const float4*)(m + (size_t)e * 128) + lane);
        float v0, v1, v2, v3;
        asm("mov.b64 {%0, %1}, %2;" : "=f"(v0), "=f"(v1) : "l"(acc0));
        asm("mov.b64 {%0, %1}, %2;" : "=f"(v2), "=f"(v3) : "l"(acc1));
        v0 *= mv.x; v1 *= mv.y; v2 *= mv.z; v3 *= mv.w;

        float* dst = out + (size_t)atom * 128 + c0;
        asm volatile("red.global.add.v4.f32 [%0], {%1, %2, %3, %4};"
                     :: "l"(dst), "f"(v0), "f"(v1), "f"(v2), "f"(v3) : "memory");
    }
}

// ============================ HMMA MLP ======================================
// out[r,c] = post( sum_k X[r,k] * W[c,k] ),  128x128 tile per CTA.
// bf16 split: X = Xh + Xl, W = Wh + Wl;  D = Xh*Wh + Xl*Wh + Xh*Wl (f32 acc).
// mma.sync.m16n8k16.row.col: A-frag = pairs of consecutive k in row r of X;
// B-frag = pairs of consecutive k in row n of W. Both are direct LDS.32 from
// row-major bf16 smem padded to stride 136 (conflict-free for quad pattern).
// 8 warps; warp w owns rows w*16..w*16+15, all 128 cols (16 n-chunks).

#define SPAD 136                               // bf16 elements per row (128+8)
#define TILE_BF16 (128 * SPAD)                 // one split tile
#define MLP_DSMEM (4 * TILE_BF16 * 2)          // XsH, XsL, WsH, WsL (139264 B)

__global__ void __launch_bounds__(256, 1) mlp_hmma_kernel(
    const float* __restrict__ X,          // [nRows,128]
    const float* __restrict__ W,          // [128,128] row-major [out,in]
    const float* __restrict__ res,        // [nRows,128] or null
    const float* __restrict__ scale_ptr,  // scalar or null
    float*       __restrict__ out,        // [nRows,128]
    int nRows)
{
    extern __shared__ __align__(16) __nv_bfloat16 smem[];
    __nv_bfloat16* XsH = smem;
    __nv_bfloat16* XsL = smem + TILE_BF16;
    __nv_bfloat16* WsH = smem + 2 * TILE_BF16;
    __nv_bfloat16* WsL = smem + 3 * TILE_BF16;

    const int tid  = threadIdx.x;
    const int row0 = blockIdx.x * 128;

    // ---- load + split: i -> (row = i>>5, k4 = i&31), float4 at k = 4*k4
    for (int i = tid; i < 128 * 32; i += 256) {
        int row = i >> 5, k4 = i & 31;
        int so = row * SPAD + 4 * k4;

        float4 v = make_float4(0.f, 0.f, 0.f, 0.f);
        if (row0 + row < nRows)
            v = __ldg((const float4*)(X + (size_t)(row0 + row) * 128) + k4);
        __nv_bfloat16 h0 = __float2bfloat16_rn(v.x);
        __nv_bfloat16 h1 = __float2bfloat16_rn(v.y);
        __nv_bfloat16 h2 = __float2bfloat16_rn(v.z);
        __nv_bfloat16 h3 = __float2bfloat16_rn(v.w);
        __nv_bfloat162 hp0 = __halves2bfloat162(h0, h1);
        __nv_bfloat162 hp1 = __halves2bfloat162(h2, h3);
        *(uint2*)&XsH[so] = make_uint2(*(uint32_t*)&hp0, *(uint32_t*)&hp1);
        __nv_bfloat162 lp0 = __halves2bfloat162(
            __float2bfloat16_rn(v.x - __bfloat162float(h0)),
            __float2bfloat16_rn(v.y - __bfloat162float(h1)));
        __nv_bfloat162 lp1 = __halves2bfloat162(
            __float2bfloat16_rn(v.z - __bfloat162float(h2)),
            __float2bfloat16_rn(v.w - __bfloat162float(h3)));
        *(uint2*)&XsL[so] = make_uint2(*(uint32_t*)&lp0, *(uint32_t*)&lp1);

        float4 w = __ldg((const float4*)(W + (size_t)row * 128) + k4);
        __nv_bfloat16 g0 = __float2bfloat16_rn(w.x);
        __nv_bfloat16 g1 = __float2bfloat16_rn(w.y);
        __nv_bfloat16 g2 = __float2bfloat16_rn(w.z);
        __nv_bfloat16 g3 = __float2bfloat16_rn(w.w);
        __nv_bfloat162 gp0 = __halves2bfloat162(g0, g1);
        __nv_bfloat162 gp1 = __halves2bfloat162(g2, g3);
        *(uint2*)&WsH[so] = make_uint2(*(uint32_t*)&gp0, *(uint32_t*)&gp1);
        __nv_bfloat162 qp0 = __halves2bfloat162(
            __float2bfloat16_rn(w.x - __bfloat162float(g0)),
            __float2bfloat16_rn(w.y - __bfloat162float(g1)));
        __nv_bfloat162 qp1 = __halves2bfloat162(
            __float2bfloat16_rn(w.z - __bfloat162float(g2)),
            __float2bfloat16_rn(w.w - __bfloat162float(g3)));
        *(uint2*)&WsL[so] = make_uint2(*(uint32_t*)&qp0, *(uint32_t*)&qp1);
    }
    __syncthreads();

    // ---- mma mainloop
    const int wid  = tid >> 5;
    const int lane = tid & 31;
    const int g    = lane >> 2;      // 0..7
    const int ti   = lane & 3;       // 0..3
    const int m0   = wid * 16;

    float d[16][4];
#pragma unroll
    for (int nc = 0; nc < 16; ++nc)
#pragma unroll
        for (int j = 0; j < 4; ++j) d[nc][j] = 0.f;

#pragma unroll
    for (int term = 0; term < 3; ++term) {
        const __nv_bfloat16* As = (term == 1) ? XsL : XsH;
        const __nv_bfloat16* Bs = (term == 2) ? WsL : WsH;
#pragma unroll
        for (int ks = 0; ks < 8; ++ks) {
            const int k0 = ks * 16;
            uint32_t a0 = *(const uint32_t*)&As[(m0 + g)     * SPAD + k0 + 2 * ti];
            uint32_t a1 = *(const uint32_t*)&As[(m0 + g + 8) * SPAD + k0 + 2 * ti];
            uint32_t a2 = *(const uint32_t*)&As[(m0 + g)     * SPAD + k0 + 2 * ti + 8];
            uint32_t a3 = *(const uint32_t*)&As[(m0 + g + 8) * SPAD + k0 + 2 * ti + 8];
#pragma unroll
            for (int nc = 0; nc < 16; ++nc) {
                uint32_t b0 = *(const uint32_t*)&Bs[(nc * 8 + g) * SPAD + k0 + 2 * ti];
                uint32_t b1 = *(const uint32_t*)&Bs[(nc * 8 + g) * SPAD + k0 + 2 * ti + 8];
                asm volatile(
                    "mma.sync.aligned.m16n8k16.row.col.f32.bf16.bf16.f32 "
                    "{%0,%1,%2,%3}, {%4,%5,%6,%7}, {%8,%9}, {%0,%1,%2,%3};"
                    : "+f"(d[nc][0]), "+f"(d[nc][1]), "+f"(d[nc][2]), "+f"(d[nc][3])
                    : "r"(a0), "r"(a1), "r"(a2), "r"(a3), "r"(b0), "r"(b1));
            }
        }
    }

    // ---- epilogue
    const float pre = scale_ptr ? __ldg(scale_ptr) : 1.0f;
    const float inv_sqrt2 = 0.70710678118654752440f;
    const int ra = row0 + m0 + g;       // rows for d[..][0..1]
    const int rb = ra + 8;              // rows for d[..][2..3]

#pragma unroll
    for (int nc = 0; nc < 16; ++nc) {
        const int c = nc * 8 + 2 * ti;
        if (ra < nRows) {
            float2 y;
            y.x = ssilu(pre * d[nc][0]);
            y.y = ssilu(pre * d[nc][1]);
            if (res) {
                float2 rv = *(const float2*)&res[(size_t)ra * 128 + c];
                y.x = (rv.x + y.x) * inv_sqrt2;
                y.y = (rv.y + y.y) * inv_sqrt2;
            }
            *(float2*)&out[(size_t)ra * 128 + c] = y;
        }
        if (rb < nRows) {
            float2 y;
            y.x = ssilu(pre * d[nc][2]);
            y.y = ssilu(pre * d[nc][3]);
            if (res) {
                float2 rv = *(const float2*)&res[(size_t)rb * 128 + c];
                y.x = (rv.x + y.x) * inv_sqrt2;
                y.y = (rv.y + y.y) * inv_sqrt2;
            }
            *(float2*)&out[(size_t)rb * 128 + c] = y;
        }
    }
}

// ---------------------------------------------------------------------------
extern "C" void kernel_launch(void* const* d_in, const int* in_sizes, int n_in,
                              void* d_out, int out_size)
{
    // metadata order: nAtoms, m, rbf, id_j, W_rbf, scale, W1, W_res
    const float* m     = (const float*)d_in[1];
    const float* rbf   = (const float*)d_in[2];
    const int*   idj   = (const int*)  d_in[3];
    const float* Wrbf  = (const float*)d_in[4];
    const float* scale = (const float*)d_in[5];
    const float* W1    = (const float*)d_in[6];
    const float* Wres  = (const float*)d_in[7];

    int E      = in_sizes[1] / 128;
    int nAtoms = out_size / 128;
    if (nAtoms > CAP_ATOMS) nAtoms = CAP_ATOMS;

    float *px2 = nullptr, *pa = nullptr, *pb = nullptr;
    cudaGetSymbolAddress((void**)&px2, g_x2);
    cudaGetSymbolAddress((void**)&pa,  g_a);
    cudaGetSymbolAddress((void**)&pb,  g_b);

    cudaFuncSetAttribute(mlp_hmma_kernel,
                         cudaFuncAttributeMaxDynamicSharedMemorySize, MLP_DSMEM);

    int n4 = nAtoms * 128 / 4;
    zero_kernel<<<2048, 256>>>(px2, n4);
    edge_kernel<<<4096, 256>>>(m, rbf, idj, Wrbf, px2, E);

    int grid = (nAtoms + 127) / 128;
    float* dout = (float*)d_out;
    mlp_hmma_kernel<<<grid, 256, MLP_DSMEM>>>(px2, W1, nullptr, scale, pa, nAtoms);
    mlp_hmma_kernel<<<grid, 256, MLP_DSMEM>>>(pa, Wres + 0 * 16384, nullptr, nullptr, pb, nAtoms);
    mlp_hmma_kernel<<<grid, 256, MLP_DSMEM>>>(pb, Wres + 1 * 16384, pa, nullptr, px2, nAtoms);
    mlp_hmma_kernel<<<grid, 256, MLP_DSMEM>>>(px2, Wres + 2 * 16384, nullptr, nullptr, pb, nAtoms);
    mlp_hmma_kernel<<<grid, 256, MLP_DSMEM>>>(pb, Wres + 3 * 16384, px2, nullptr, dout, nAtoms);
}

// round 5
// speedup vs baseline: 1.8118x; 1.4496x over previous
#include <cuda_runtime.h>
#include <cuda_bf16.h>
#include <cstdint>

// ---------------------------------------------------------------------------
// AtomUpdateBlock on GB300 (plain sm_103 feature set).
// Edge stage (R1-proven): zero + warp-per-edge FFMA2 + red.global.add.v4.f32.
// MLP stage: ONE fused kernel, 5 chained 128x128 GEMM layers per CTA,
//            bf16-split HMMA (D = XhWh + XlWh + XhWl, f32 accum),
//            512 threads, warp tile 32x32, activations never leave the SM.
// ---------------------------------------------------------------------------

#define CAP_ATOMS 131072
__device__ float g_x2[CAP_ATOMS * 128];

__device__ __forceinline__ float ssilu(float x) {
    return x * (1.0f / (1.0f + __expf(-x))) * 1.6666666666666667f;
}

// ============================ edge stage ====================================
__global__ void __launch_bounds__(256) zero_kernel(float* __restrict__ p, int n4) {
    int i = blockIdx.x * blockDim.x + threadIdx.x;
    int stride = gridDim.x * blockDim.x;
    float4 z = make_float4(0.f, 0.f, 0.f, 0.f);
    for (; i < n4; i += stride) ((float4*)p)[i] = z;
}

__global__ void __launch_bounds__(256) edge_kernel(
    const float* __restrict__ m,      // [E,128]
    const float* __restrict__ rbf,    // [E,16]
    const int*   __restrict__ idj,    // [E]
    const float* __restrict__ Wr,     // [128,16]
    float*       __restrict__ out,    // [nAtoms,128]
    int E)
{
    const int lane  = threadIdx.x & 31;
    const int warp  = (blockIdx.x * blockDim.x + threadIdx.x) >> 5;
    const int nwarp = (gridDim.x * blockDim.x) >> 5;
    const int c0 = lane * 4;

    unsigned long long wp0[16], wp1[16];
#pragma unroll
    for (int k = 0; k < 16; ++k) {
        float a = Wr[(c0 + 0) * 16 + k];
        float b = Wr[(c0 + 1) * 16 + k];
        float c = Wr[(c0 + 2) * 16 + k];
        float d = Wr[(c0 + 3) * 16 + k];
        asm("mov.b64 %0, {%1, %2};" : "=l"(wp0[k]) : "f"(a), "f"(b));
        asm("mov.b64 %0, {%1, %2};" : "=l"(wp1[k]) : "f"(c), "f"(d));
    }

    for (int e = warp; e < E; e += nwarp) {
        const int atom = __ldg(idj + e);
        const float4* rb4 = (const float4*)(rbf + (size_t)e * 16);
        float4 r0 = __ldg(rb4 + 0);
        float4 r1 = __ldg(rb4 + 1);
        float4 r2 = __ldg(rb4 + 2);
        float4 r3 = __ldg(rb4 + 3);
        float rk[16];
        rk[0]=r0.x; rk[1]=r0.y; rk[2]=r0.z; rk[3]=r0.w;
        rk[4]=r1.x; rk[5]=r1.y; rk[6]=r1.z; rk[7]=r1.w;
        rk[8]=r2.x; rk[9]=r2.y; rk[10]=r2.z; rk[11]=r2.w;
        rk[12]=r3.x; rk[13]=r3.y; rk[14]=r3.z; rk[15]=r3.w;

        unsigned long long acc0 = 0ull, acc1 = 0ull;
#pragma unroll
        for (int k = 0; k < 16; ++k) {
            unsigned long long rp;
            asm("mov.b64 %0, {%1, %1};" : "=l"(rp) : "f"(rk[k]));
            asm("fma.rn.f32x2 %0, %1, %2, %0;" : "+l"(acc0) : "l"(rp), "l"(wp0[k]));
            asm("fma.rn.f32x2 %0, %1, %2, %0;" : "+l"(acc1) : "l"(rp), "l"(wp1[k]));
        }

        float4 mv = __ldg((const float4*)(m + (size_t)e * 128) + lane);
        float v0, v1, v2, v3;
        asm("mov.b64 {%0, %1}, %2;" : "=f"(v0), "=f"(v1) : "l"(acc0));
        asm("mov.b64 {%0, %1}, %2;" : "=f"(v2), "=f"(v3) : "l"(acc1));
        v0 *= mv.x; v1 *= mv.y; v2 *= mv.z; v3 *= mv.w;

        float* dst = out + (size_t)atom * 128 + c0;
        asm volatile("red.global.add.v4.f32 [%0], {%1, %2, %3, %4};"
                     :: "l"(dst), "f"(v0), "f"(v1), "f"(v2), "f"(v3) : "memory");
    }
}

// ============================ fused MLP =====================================
#define SPAD 136                       // bf16 elems per smem row (128+8)
#define TILE (128 * SPAD)              // elems per tile
#define MLP_DSMEM (4 * TILE * 2)       // XsH XsL WsH WsL = 139264 B

__device__ __forceinline__ void split_store(
    __nv_bfloat16* __restrict__ hi, __nv_bfloat16* __restrict__ lo,
    int idx, float x, float y)
{
    __nv_bfloat16 hx = __float2bfloat16_rn(x);
    __nv_bfloat16 hy = __float2bfloat16_rn(y);
    __nv_bfloat162 hp = __halves2bfloat162(hx, hy);
    __nv_bfloat162 lp = __halves2bfloat162(
        __float2bfloat16_rn(x - __bfloat162float(hx)),
        __float2bfloat16_rn(y - __bfloat162float(hy)));
    *(uint32_t*)&hi[idx] = *(uint32_t*)&hp;
    *(uint32_t*)&lo[idx] = *(uint32_t*)&lp;
}

__device__ __forceinline__ void load_w_split(
    const float* __restrict__ W, __nv_bfloat16* __restrict__ WsH,
    __nv_bfloat16* __restrict__ WsL, int tid)
{
    for (int i = tid; i < 128 * 32; i += 512) {
        int row = i >> 5, k4 = i & 31;
        int so = row * SPAD + 4 * k4;
        float4 w = __ldg((const float4*)(W + (size_t)row * 128) + k4);
        split_store(WsH, WsL, so,     w.x, w.y);
        split_store(WsH, WsL, so + 2, w.z, w.w);
    }
}

__global__ void __launch_bounds__(512, 1) fused_mlp_kernel(
    const float* __restrict__ X,          // [nRows,128] (x2)
    const float* __restrict__ W1,         // [128,128]
    const float* __restrict__ Wres,       // [4,128,128]
    const float* __restrict__ scale_ptr,  // scalar
    float*       __restrict__ out,        // [nRows,128]
    int nRows)
{
    extern __shared__ __align__(16) __nv_bfloat16 smem[];
    __nv_bfloat16* XsH = smem;
    __nv_bfloat16* XsL = smem + TILE;
    __nv_bfloat16* WsH = smem + 2 * TILE;
    __nv_bfloat16* WsL = smem + 3 * TILE;

    const int tid  = threadIdx.x;
    const int row0 = blockIdx.x * 128;

    // ---- initial loads: x2 tile + layer-0 weights (split to bf16 pairs)
    for (int i = tid; i < 128 * 32; i += 512) {
        int row = i >> 5, k4 = i & 31;
        int so = row * SPAD + 4 * k4;
        float4 v = make_float4(0.f, 0.f, 0.f, 0.f);
        if (row0 + row < nRows)
            v = __ldg((const float4*)(X + (size_t)(row0 + row) * 128) + k4);
        split_store(XsH, XsL, so,     v.x, v.y);
        split_store(XsH, XsL, so + 2, v.z, v.w);
    }
    load_w_split(W1, WsH, WsL, tid);

    // ---- warp tiling: 16 warps = 4 row-groups x 4 col-groups, 32x32 each
    const int wid  = tid >> 5;
    const int lane = tid & 31;
    const int g    = lane >> 2;          // 0..7
    const int ti   = lane & 3;           // 0..3
    const int m0   = (wid & 3) * 32;     // local row base
    const int nb   = (wid >> 2) * 32;    // col base (4 nc chunks of 8)

    const float pre0 = scale_ptr ? __ldg(scale_ptr) : 1.0f;
    const float inv_sqrt2 = 0.70710678118654752440f;

    float res[2][4][4];                  // residual y (layer 0 / layer 2 output)

#pragma unroll 1
    for (int L = 0; L < 5; ++L) {
        __syncthreads();                 // Xs/Ws stores visible

        float d[2][4][4];
#pragma unroll
        for (int mt = 0; mt < 2; ++mt)
#pragma unroll
            for (int nc = 0; nc < 4; ++nc)
#pragma unroll
                for (int j = 0; j < 4; ++j) d[mt][nc][j] = 0.f;

#pragma unroll
        for (int ks = 0; ks < 8; ++ks) {
            const int k0 = ks * 16;
            uint32_t ah[2][4], al[2][4];
#pragma unroll
            for (int mt = 0; mt < 2; ++mt) {
                const int r = m0 + 16 * mt + g;
                ah[mt][0] = *(const uint32_t*)&XsH[(r)     * SPAD + k0 + 2 * ti];
                ah[mt][1] = *(const uint32_t*)&XsH[(r + 8) * SPAD + k0 + 2 * ti];
                ah[mt][2] = *(const uint32_t*)&XsH[(r)     * SPAD + k0 + 2 * ti + 8];
                ah[mt][3] = *(const uint32_t*)&XsH[(r + 8) * SPAD + k0 + 2 * ti + 8];
                al[mt][0] = *(const uint32_t*)&XsL[(r)     * SPAD + k0 + 2 * ti];
                al[mt][1] = *(const uint32_t*)&XsL[(r + 8) * SPAD + k0 + 2 * ti];
                al[mt][2] = *(const uint32_t*)&XsL[(r)     * SPAD + k0 + 2 * ti + 8];
                al[mt][3] = *(const uint32_t*)&XsL[(r + 8) * SPAD + k0 + 2 * ti + 8];
            }
            // terms XhWh + XlWh (shared Wh frags)
#pragma unroll
            for (int nc = 0; nc < 4; ++nc) {
                const int n = nb + 8 * nc + g;
                uint32_t b0 = *(const uint32_t*)&WsH[n * SPAD + k0 + 2 * ti];
                uint32_t b1 = *(const uint32_t*)&WsH[n * SPAD + k0 + 2 * ti + 8];
#pragma unroll
                for (int mt = 0; mt < 2; ++mt) {
                    asm volatile(
                        "mma.sync.aligned.m16n8k16.row.col.f32.bf16.bf16.f32 "
                        "{%0,%1,%2,%3}, {%4,%5,%6,%7}, {%8,%9}, {%0,%1,%2,%3};"
                        : "+f"(d[mt][nc][0]), "+f"(d[mt][nc][1]),
                          "+f"(d[mt][nc][2]), "+f"(d[mt][nc][3])
                        : "r"(ah[mt][0]), "r"(ah[mt][1]), "r"(ah[mt][2]), "r"(ah[mt][3]),
                          "r"(b0), "r"(b1));
                    asm volatile(
                        "mma.sync.aligned.m16n8k16.row.col.f32.bf16.bf16.f32 "
                        "{%0,%1,%2,%3}, {%4,%5,%6,%7}, {%8,%9}, {%0,%1,%2,%3};"
                        : "+f"(d[mt][nc][0]), "+f"(d[mt][nc][1]),
                          "+f"(d[mt][nc][2]), "+f"(d[mt][nc][3])
                        : "r"(al[mt][0]), "r"(al[mt][1]), "r"(al[mt][2]), "r"(al[mt][3]),
                          "r"(b0), "r"(b1));
                }
            }
            // term XhWl
#pragma unroll
            for (int nc = 0; nc < 4; ++nc) {
                const int n = nb + 8 * nc + g;
                uint32_t b0 = *(const uint32_t*)&WsL[n * SPAD + k0 + 2 * ti];
                uint32_t b1 = *(const uint32_t*)&WsL[n * SPAD + k0 + 2 * ti + 8];
#pragma unroll
                for (int mt = 0; mt < 2; ++mt) {
                    asm volatile(
                        "mma.sync.aligned.m16n8k16.row.col.f32.bf16.bf16.f32 "
                        "{%0,%1,%2,%3}, {%4,%5,%6,%7}, {%8,%9}, {%0,%1,%2,%3};"
                        : "+f"(d[mt][nc][0]), "+f"(d[mt][nc][1]),
                          "+f"(d[mt][nc][2]), "+f"(d[mt][nc][3])
                        : "r"(ah[mt][0]), "r"(ah[mt][1]), "r"(ah[mt][2]), "r"(ah[mt][3]),
                          "r"(b0), "r"(b1));
                }
            }
        }

        __syncthreads();                 // everyone done reading Xs/Ws

        // ---- epilogue: activation (+residual), produce next-layer input
        const float pre   = (L == 0) ? pre0 : 1.0f;
        const bool addres = (L == 2) || (L == 4);
        const bool saver  = (L == 0) || (L == 2);

#pragma unroll
        for (int mt = 0; mt < 2; ++mt) {
#pragma unroll
            for (int nc = 0; nc < 4; ++nc) {
                float v[4];
#pragma unroll
                for (int j = 0; j < 4; ++j) {
                    float y = ssilu(pre * d[mt][nc][j]);
                    if (addres) y = (res[mt][nc][j] + y) * inv_sqrt2;
                    if (saver)  res[mt][nc][j] = y;
                    v[j] = y;
                }
                const int ra = m0 + 16 * mt + g;        // local rows
                const int rb = ra + 8;
                const int c  = nb + 8 * nc + 2 * ti;
                if (L < 4) {
                    split_store(XsH, XsL, ra * SPAD + c, v[0], v[1]);
                    split_store(XsH, XsL, rb * SPAD + c, v[2], v[3]);
                } else {
                    if (row0 + ra < nRows)
                        *(float2*)&out[(size_t)(row0 + ra) * 128 + c] =
                            make_float2(v[0], v[1]);
                    if (row0 + rb < nRows)
                        *(float2*)&out[(size_t)(row0 + rb) * 128 + c] =
                            make_float2(v[2], v[3]);
                }
            }
        }

        if (L < 4) load_w_split(Wres + (size_t)L * 16384, WsH, WsL, tid);
    }
}

// ---------------------------------------------------------------------------
extern "C" void kernel_launch(void* const* d_in, const int* in_sizes, int n_in,
                              void* d_out, int out_size)
{
    // metadata order: nAtoms, m, rbf, id_j, W_rbf, scale, W1, W_res
    const float* m     = (const float*)d_in[1];
    const float* rbf   = (const float*)d_in[2];
    const int*   idj   = (const int*)  d_in[3];
    const float* Wrbf  = (const float*)d_in[4];
    const float* scale = (const float*)d_in[5];
    const float* W1    = (const float*)d_in[6];
    const float* Wres  = (const float*)d_in[7];

    int E      = in_sizes[1] / 128;
    int nAtoms = out_size / 128;
    if (nAtoms > CAP_ATOMS) nAtoms = CAP_ATOMS;

    float* px2 = nullptr;
    cudaGetSymbolAddress((void**)&px2, g_x2);

    cudaFuncSetAttribute(fused_mlp_kernel,
                         cudaFuncAttributeMaxDynamicSharedMemorySize, MLP_DSMEM);

    int n4 = nAtoms * 128 / 4;
    zero_kernel<<<2048, 256>>>(px2, n4);
    edge_kernel<<<4096, 256>>>(m, rbf, idj, Wrbf, px2, E);

    int grid = (nAtoms + 127) / 128;
    fused_mlp_kernel<<<grid, 512, MLP_DSMEM>>>(px2, W1, Wres, scale,
                                               (float*)d_out, nAtoms);
}

// round 6
// speedup vs baseline: 2.2221x; 1.2264x over previous
#include <cuda_runtime.h>
#include <cuda_bf16.h>
#include <cstdint>

// ---------------------------------------------------------------------------
// AtomUpdateBlock on GB300 (plain sm_103 feature set).
// Edge stage: CSR sort (int atomics) + edge-parallel run-accumulated scatter
//             (atomic f32 ops reduced ~9x vs R1 path).
// MLP stage: ONE fused kernel, 5 chained 128x128 GEMM layers per CTA,
//            bf16-split HMMA, 512 threads, warp tile 32x32 (R5-proven).
// ---------------------------------------------------------------------------

#define CAP_ATOMS 131072
#define CAP_EDGES (1 << 21)

__device__ float g_x2[CAP_ATOMS * 128];
__device__ int   g_counts[CAP_ATOMS];
__device__ int   g_offs  [CAP_ATOMS];
__device__ int   g_cursor[CAP_ATOMS];
__device__ int   g_bsums [256];
__device__ int   g_eids  [CAP_EDGES];
__device__ int   g_aids  [CAP_EDGES];

__device__ __forceinline__ float ssilu(float x) {
    return x * (1.0f / (1.0f + __expf(-x))) * 1.6666666666666667f;
}

// ============================ zero / CSR build ==============================
__global__ void __launch_bounds__(256) zero_kernel(float* __restrict__ p, int n4) {
    int i = blockIdx.x * blockDim.x + threadIdx.x;
    int stride = gridDim.x * blockDim.x;
    float4 z = make_float4(0.f, 0.f, 0.f, 0.f);
    for (; i < n4; i += stride) ((float4*)p)[i] = z;
}

__global__ void __launch_bounds__(256) zero_int_kernel(int* __restrict__ p, int n4) {
    int i = blockIdx.x * blockDim.x + threadIdx.x;
    int stride = gridDim.x * blockDim.x;
    int4 z = make_int4(0, 0, 0, 0);
    for (; i < n4; i += stride) ((int4*)p)[i] = z;
}

__global__ void __launch_bounds__(256) hist_kernel(const int* __restrict__ idj,
                                                   int* __restrict__ counts, int E) {
    int i = blockIdx.x * blockDim.x + threadIdx.x;
    int stride = gridDim.x * blockDim.x;
    for (; i < E; i += stride) atomicAdd(&counts[__ldg(idj + i)], 1);
}

__global__ void __launch_bounds__(256) scan1_kernel(const int* __restrict__ counts,
                                                    int* __restrict__ offs,
                                                    int* __restrict__ bsums, int nAtoms) {
    __shared__ int sm[256];
    int t = threadIdx.x;
    int base = blockIdx.x * 1024 + t * 4;
    int c0 = 0, c1 = 0, c2 = 0, c3 = 0;
    if (base + 3 < nAtoms) {
        int4 c = *(const int4*)(counts + base);
        c0 = c.x; c1 = c.y; c2 = c.z; c3 = c.w;
    } else {
        if (base + 0 < nAtoms) c0 = counts[base + 0];
        if (base + 1 < nAtoms) c1 = counts[base + 1];
        if (base + 2 < nAtoms) c2 = counts[base + 2];
        if (base + 3 < nAtoms) c3 = counts[base + 3];
    }
    int T = c0 + c1 + c2 + c3;
    sm[t] = T;
    __syncthreads();
    for (int d = 1; d < 256; d <<= 1) {
        int v = (t >= d) ? sm[t - d] : 0;
        __syncthreads();
        sm[t] += v;
        __syncthreads();
    }
    int o = sm[t] - T;
    if (t == 255) bsums[blockIdx.x] = sm[255];
    if (base + 0 < nAtoms) offs[base + 0] = o; o += c0;
    if (base + 1 < nAtoms) offs[base + 1] = o; o += c1;
    if (base + 2 < nAtoms) offs[base + 2] = o; o += c2;
    if (base + 3 < nAtoms) offs[base + 3] = o;
}

__global__ void __launch_bounds__(128) scan2_kernel(int* __restrict__ bsums, int nb) {
    __shared__ int sm[128];
    int t = threadIdx.x;
    int v = (t < nb) ? bsums[t] : 0;
    sm[t] = v;
    __syncthreads();
    for (int d = 1; d < 128; d <<= 1) {
        int x = (t >= d) ? sm[t - d] : 0;
        __syncthreads();
        sm[t] += x;
        __syncthreads();
    }
    bsums[t] = sm[t] - v;
}

__global__ void __launch_bounds__(256) scan3_kernel(const int* __restrict__ bsums,
                                                    int* __restrict__ offs,
                                                    int* __restrict__ cursor,
                                                    int nAtoms) {
    int i = blockIdx.x * blockDim.x + threadIdx.x;
    if (i < nAtoms) {
        int v = offs[i] + __ldg(bsums + (i >> 10));
        offs[i] = v;
        cursor[i] = v;
    }
}

__global__ void __launch_bounds__(256) fill_kernel(const int* __restrict__ idj,
                                                   int* __restrict__ cursor,
                                                   int* __restrict__ eids,
                                                   int* __restrict__ aids, int E) {
    int i = blockIdx.x * blockDim.x + threadIdx.x;
    int stride = gridDim.x * blockDim.x;
    for (; i < E; i += stride) {
        int a = __ldg(idj + i);
        int p = atomicAdd(&cursor[a], 1);
        eids[p] = i;
        aids[p] = a;
    }
}

// ============================ sorted edge scatter ===========================
// One warp per CHUNK sorted edges. Lane owns channels 4L..4L+3. Consecutive
// same-atom edges accumulate in registers; red.global.add.v4 only at run
// boundaries (~E/10 + E/CHUNK flushes instead of E).
#define CHUNK 64

__global__ void __launch_bounds__(256) edge_sorted_kernel(
    const float* __restrict__ m,      // [E,128]
    const float* __restrict__ rbf,    // [E,16]
    const int*   __restrict__ eids,   // [E] sorted by atom
    const int*   __restrict__ aids,   // [E] atom per sorted slot
    const float* __restrict__ Wr,     // [128,16]
    float*       __restrict__ out,    // [nAtoms,128] accumulator (zeroed)
    int E)
{
    const int lane  = threadIdx.x & 31;
    const int warp  = (blockIdx.x * blockDim.x + threadIdx.x) >> 5;
    const int base  = warp * CHUNK;
    if (base >= E) return;
    const int end = (base + CHUNK < E) ? base + CHUNK : E;
    const int c0 = lane * 4;

    unsigned long long wp0[16], wp1[16];
#pragma unroll
    for (int k = 0; k < 16; ++k) {
        float a = __ldg(&Wr[(c0 + 0) * 16 + k]);
        float b = __ldg(&Wr[(c0 + 1) * 16 + k]);
        float c = __ldg(&Wr[(c0 + 2) * 16 + k]);
        float d = __ldg(&Wr[(c0 + 3) * 16 + k]);
        asm("mov.b64 %0, {%1, %2};" : "=l"(wp0[k]) : "f"(a), "f"(b));
        asm("mov.b64 %0, {%1, %2};" : "=l"(wp1[k]) : "f"(c), "f"(d));
    }

    int cur = __ldg(aids + base);
    float ax = 0.f, ay = 0.f, az = 0.f, aw = 0.f;

    for (int i = base; i < end; ++i) {
        const int a = __ldg(aids + i);
        if (a != cur) {                      // warp-uniform branch
            float* dst = out + (size_t)cur * 128 + c0;
            asm volatile("red.global.add.v4.f32 [%0], {%1, %2, %3, %4};"
                         :: "l"(dst), "f"(ax), "f"(ay), "f"(az), "f"(aw) : "memory");
            ax = ay = az = aw = 0.f;
            cur = a;
        }
        const int e = __ldg(eids + i);
        const float4* rb4 = (const float4*)(rbf + (size_t)e * 16);
        float4 r0 = __ldg(rb4 + 0);
        float4 r1 = __ldg(rb4 + 1);
        float4 r2 = __ldg(rb4 + 2);
        float4 r3 = __ldg(rb4 + 3);
        float4 mv = __ldg((const float4*)(m + (size_t)e * 128) + lane);

        float rk[16];
        rk[0]=r0.x; rk[1]=r0.y; rk[2]=r0.z; rk[3]=r0.w;
        rk[4]=r1.x; rk[5]=r1.y; rk[6]=r1.z; rk[7]=r1.w;
        rk[8]=r2.x; rk[9]=r2.y; rk[10]=r2.z; rk[11]=r2.w;
        rk[12]=r3.x; rk[13]=r3.y; rk[14]=r3.z; rk[15]=r3.w;

        unsigned long long d01 = 0ull, d23 = 0ull;
#pragma unroll
        for (int k = 0; k < 16; ++k) {
            unsigned long long rp;
            asm("mov.b64 %0, {%1, %1};" : "=l"(rp) : "f"(rk[k]));
            asm("fma.rn.f32x2 %0, %1, %2, %0;" : "+l"(d01) : "l"(rp), "l"(wp0[k]));
            asm("fma.rn.f32x2 %0, %1, %2, %0;" : "+l"(d23) : "l"(rp), "l"(wp1[k]));
        }
        float v0, v1, v2, v3;
        asm("mov.b64 {%0, %1}, %2;" : "=f"(v0), "=f"(v1) : "l"(d01));
        asm("mov.b64 {%0, %1}, %2;" : "=f"(v2), "=f"(v3) : "l"(d23));
        ax = fmaf(v0, mv.x, ax);
        ay = fmaf(v1, mv.y, ay);
        az = fmaf(v2, mv.z, az);
        aw = fmaf(v3, mv.w, aw);
    }
    float* dst = out + (size_t)cur * 128 + c0;
    asm volatile("red.global.add.v4.f32 [%0], {%1, %2, %3, %4};"
                 :: "l"(dst), "f"(ax), "f"(ay), "f"(az), "f"(aw) : "memory");
}

// ============================ fused MLP (R5) ================================
#define SPAD 136
#define TILE (128 * SPAD)
#define MLP_DSMEM (4 * TILE * 2)

__device__ __forceinline__ void split_store(
    __nv_bfloat16* __restrict__ hi, __nv_bfloat16* __restrict__ lo,
    int idx, float x, float y)
{
    __nv_bfloat16 hx = __float2bfloat16_rn(x);
    __nv_bfloat16 hy = __float2bfloat16_rn(y);
    __nv_bfloat162 hp = __halves2bfloat162(hx, hy);
    __nv_bfloat162 lp = __halves2bfloat162(
        __float2bfloat16_rn(x - __bfloat162float(hx)),
        __float2bfloat16_rn(y - __bfloat162float(hy)));
    *(uint32_t*)&hi[idx] = *(uint32_t*)&hp;
    *(uint32_t*)&lo[idx] = *(uint32_t*)&lp;
}

__device__ __forceinline__ void load_w_split(
    const float* __restrict__ W, __nv_bfloat16* __restrict__ WsH,
    __nv_bfloat16* __restrict__ WsL, int tid)
{
    for (int i = tid; i < 128 * 32; i += 512) {
        int row = i >> 5, k4 = i & 31;
        int so = row * SPAD + 4 * k4;
        float4 w = __ldg((const float4*)(W + (size_t)row * 128) + k4);
        split_store(WsH, WsL, so,     w.x, w.y);
        split_store(WsH, WsL, so + 2, w.z, w.w);
    }
}

__global__ void __launch_bounds__(512, 1) fused_mlp_kernel(
    const float* __restrict__ X,
    const float* __restrict__ W1,
    const float* __restrict__ Wres,
    const float* __restrict__ scale_ptr,
    float*       __restrict__ out,
    int nRows)
{
    extern __shared__ __align__(16) __nv_bfloat16 smem[];
    __nv_bfloat16* XsH = smem;
    __nv_bfloat16* XsL = smem + TILE;
    __nv_bfloat16* WsH = smem + 2 * TILE;
    __nv_bfloat16* WsL = smem + 3 * TILE;

    const int tid  = threadIdx.x;
    const int row0 = blockIdx.x * 128;

    for (int i = tid; i < 128 * 32; i += 512) {
        int row = i >> 5, k4 = i & 31;
        int so = row * SPAD + 4 * k4;
        float4 v = make_float4(0.f, 0.f, 0.f, 0.f);
        if (row0 + row < nRows)
            v = __ldg((const float4*)(X + (size_t)(row0 + row) * 128) + k4);
        split_store(XsH, XsL, so,     v.x, v.y);
        split_store(XsH, XsL, so + 2, v.z, v.w);
    }
    load_w_split(W1, WsH, WsL, tid);

    const int wid  = tid >> 5;
    const int lane = tid & 31;
    const int g    = lane >> 2;
    const int ti   = lane & 3;
    const int m0   = (wid & 3) * 32;
    const int nb   = (wid >> 2) * 32;

    const float pre0 = scale_ptr ? __ldg(scale_ptr) : 1.0f;
    const float inv_sqrt2 = 0.70710678118654752440f;

    float res[2][4][4];

#pragma unroll 1
    for (int L = 0; L < 5; ++L) {
        __syncthreads();

        float d[2][4][4];
#pragma unroll
        for (int mt = 0; mt < 2; ++mt)
#pragma unroll
            for (int nc = 0; nc < 4; ++nc)
#pragma unroll
                for (int j = 0; j < 4; ++j) d[mt][nc][j] = 0.f;

#pragma unroll
        for (int ks = 0; ks < 8; ++ks) {
            const int k0 = ks * 16;
            uint32_t ah[2][4], al[2][4];
#pragma unroll
            for (int mt = 0; mt < 2; ++mt) {
                const int r = m0 + 16 * mt + g;
                ah[mt][0] = *(const uint32_t*)&XsH[(r)     * SPAD + k0 + 2 * ti];
                ah[mt][1] = *(const uint32_t*)&XsH[(r + 8) * SPAD + k0 + 2 * ti];
                ah[mt][2] = *(const uint32_t*)&XsH[(r)     * SPAD + k0 + 2 * ti + 8];
                ah[mt][3] = *(const uint32_t*)&XsH[(r + 8) * SPAD + k0 + 2 * ti + 8];
                al[mt][0] = *(const uint32_t*)&XsL[(r)     * SPAD + k0 + 2 * ti];
                al[mt][1] = *(const uint32_t*)&XsL[(r + 8) * SPAD + k0 + 2 * ti];
                al[mt][2] = *(const uint32_t*)&XsL[(r)     * SPAD + k0 + 2 * ti + 8];
                al[mt][3] = *(const uint32_t*)&XsL[(r + 8) * SPAD + k0 + 2 * ti + 8];
            }
#pragma unroll
            for (int nc = 0; nc < 4; ++nc) {
                const int n = nb + 8 * nc + g;
                uint32_t b0 = *(const uint32_t*)&WsH[n * SPAD + k0 + 2 * ti];
                uint32_t b1 = *(const uint32_t*)&WsH[n * SPAD + k0 + 2 * ti + 8];
#pragma unroll
                for (int mt = 0; mt < 2; ++mt) {
                    asm volatile(
                        "mma.sync.aligned.m16n8k16.row.col.f32.bf16.bf16.f32 "
                        "{%0,%1,%2,%3}, {%4,%5,%6,%7}, {%8,%9}, {%0,%1,%2,%3};"
                        : "+f"(d[mt][nc][0]), "+f"(d[mt][nc][1]),
                          "+f"(d[mt][nc][2]), "+f"(d[mt][nc][3])
                        : "r"(ah[mt][0]), "r"(ah[mt][1]), "r"(ah[mt][2]), "r"(ah[mt][3]),
                          "r"(b0), "r"(b1));
                    asm volatile(
                        "mma.sync.aligned.m16n8k16.row.col.f32.bf16.bf16.f32 "
                        "{%0,%1,%2,%3}, {%4,%5,%6,%7}, {%8,%9}, {%0,%1,%2,%3};"
                        : "+f"(d[mt][nc][0]), "+f"(d[mt][nc][1]),
                          "+f"(d[mt][nc][2]), "+f"(d[mt][nc][3])
                        : "r"(al[mt][0]), "r"(al[mt][1]), "r"(al[mt][2]), "r"(al[mt][3]),
                          "r"(b0), "r"(b1));
                }
            }
#pragma unroll
            for (int nc = 0; nc < 4; ++nc) {
                const int n = nb + 8 * nc + g;
                uint32_t b0 = *(const uint32_t*)&WsL[n * SPAD + k0 + 2 * ti];
                uint32_t b1 = *(const uint32_t*)&WsL[n * SPAD + k0 + 2 * ti + 8];
#pragma unroll
                for (int mt = 0; mt < 2; ++mt) {
                    asm volatile(
                        "mma.sync.aligned.m16n8k16.row.col.f32.bf16.bf16.f32 "
                        "{%0,%1,%2,%3}, {%4,%5,%6,%7}, {%8,%9}, {%0,%1,%2,%3};"
                        : "+f"(d[mt][nc][0]), "+f"(d[mt][nc][1]),
                          "+f"(d[mt][nc][2]), "+f"(d[mt][nc][3])
                        : "r"(ah[mt][0]), "r"(ah[mt][1]), "r"(ah[mt][2]), "r"(ah[mt][3]),
                          "r"(b0), "r"(b1));
                }
            }
        }

        __syncthreads();

        const float pre   = (L == 0) ? pre0 : 1.0f;
        const bool addres = (L == 2) || (L == 4);
        const bool saver  = (L == 0) || (L == 2);

#pragma unroll
        for (int mt = 0; mt < 2; ++mt) {
#pragma unroll
            for (int nc = 0; nc < 4; ++nc) {
                float v[4];
#pragma unroll
                for (int j = 0; j < 4; ++j) {
                    float y = ssilu(pre * d[mt][nc][j]);
                    if (addres) y = (res[mt][nc][j] + y) * inv_sqrt2;
                    if (saver)  res[mt][nc][j] = y;
                    v[j] = y;
                }
                const int ra = m0 + 16 * mt + g;
                const int rb = ra + 8;
                const int c  = nb + 8 * nc + 2 * ti;
                if (L < 4) {
                    split_store(XsH, XsL, ra * SPAD + c, v[0], v[1]);
                    split_store(XsH, XsL, rb * SPAD + c, v[2], v[3]);
                } else {
                    if (row0 + ra < nRows)
                        *(float2*)&out[(size_t)(row0 + ra) * 128 + c] =
                            make_float2(v[0], v[1]);
                    if (row0 + rb < nRows)
                        *(float2*)&out[(size_t)(row0 + rb) * 128 + c] =
                            make_float2(v[2], v[3]);
                }
            }
        }

        if (L < 4) load_w_split(Wres + (size_t)L * 16384, WsH, WsL, tid);
    }
}

// ---------------------------------------------------------------------------
extern "C" void kernel_launch(void* const* d_in, const int* in_sizes, int n_in,
                              void* d_out, int out_size)
{
    // metadata order: nAtoms, m, rbf, id_j, W_rbf, scale, W1, W_res
    const float* m     = (const float*)d_in[1];
    const float* rbf   = (const float*)d_in[2];
    const int*   idj   = (const int*)  d_in[3];
    const float* Wrbf  = (const float*)d_in[4];
    const float* scale = (const float*)d_in[5];
    const float* W1    = (const float*)d_in[6];
    const float* Wres  = (const float*)d_in[7];

    int E      = in_sizes[1] / 128;
    int nAtoms = out_size / 128;
    if (nAtoms > CAP_ATOMS) nAtoms = CAP_ATOMS;
    if (E > CAP_EDGES) E = CAP_EDGES;

    float* px2 = nullptr;
    int *pcounts = nullptr, *poffs = nullptr, *pcursor = nullptr,
        *pbsums = nullptr, *peids = nullptr, *paids = nullptr;
    cudaGetSymbolAddress((void**)&px2, g_x2);
    cudaGetSymbolAddress((void**)&pcounts, g_counts);
    cudaGetSymbolAddress((void**)&poffs,   g_offs);
    cudaGetSymbolAddress((void**)&pcursor, g_cursor);
    cudaGetSymbolAddress((void**)&pbsums,  g_bsums);
    cudaGetSymbolAddress((void**)&peids,   g_eids);
    cudaGetSymbolAddress((void**)&paids,   g_aids);

    cudaFuncSetAttribute(fused_mlp_kernel,
                         cudaFuncAttributeMaxDynamicSharedMemorySize, MLP_DSMEM);

    // CSR sort of edges by atom
    zero_int_kernel<<<256, 256>>>(pcounts, CAP_ATOMS / 4);
    hist_kernel<<<2048, 256>>>(idj, pcounts, E);
    int nb = (nAtoms + 1023) / 1024;
    scan1_kernel<<<nb, 256>>>(pcounts, poffs, pbsums, nAtoms);
    scan2_kernel<<<1, 128>>>(pbsums, nb);
    scan3_kernel<<<(nAtoms + 255) / 256, 256>>>(pbsums, poffs, pcursor, nAtoms);
    fill_kernel<<<2048, 256>>>(idj, pcursor, peids, paids, E);

    // zero accumulator + run-accumulated scatter
    int n4 = nAtoms * 128 / 4;
    zero_kernel<<<2048, 256>>>(px2, n4);
    int nchunks = (E + CHUNK - 1) / CHUNK;
    edge_sorted_kernel<<<(nchunks + 7) / 8, 256>>>(m, rbf, peids, paids, Wrbf,
                                                   px2, E);

    // fused MLP
    int grid = (nAtoms + 127) / 128;
    fused_mlp_kernel<<<grid, 512, MLP_DSMEM>>>(px2, W1, Wres, scale,
                                               (float*)d_out, nAtoms);
}